// round 1
// baseline (speedup 1.0000x reference)
#include <cuda_runtime.h>

#define B_ROWS 2048
#define THREADS 256
#define RPT 8            // rows per thread = B_ROWS/THREADS
#define DC 16            // d-chunk staged in smem
#define XPAD 17          // padded row stride (floats) for sh_x
#define BN_EPS 1e-5f

typedef unsigned long long ull;

__device__ __forceinline__ ull pack2(float lo, float hi) {
    ull r; asm("mov.b64 %0, {%1, %2};" : "=l"(r) : "f"(lo), "f"(hi)); return r;
}
__device__ __forceinline__ void unpack2(ull v, float& lo, float& hi) {
    asm("mov.b64 {%0, %1}, %2;" : "=f"(lo), "=f"(hi) : "l"(v));
}
__device__ __forceinline__ ull fma2(ull a, ull b, ull c) {
    ull d; asm("fma.rn.f32x2 %0, %1, %2, %3;" : "=l"(d) : "l"(a), "l"(b), "l"(c)); return d;
}
// accurate-enough tanh: abs err ~1e-6 (vs tanh.approx ~5e-4 which is too close to the 1e-3 gate)
__device__ __forceinline__ float ftanh(float x) {
    float e = __expf(2.0f * x);
    return 1.0f - __fdividef(2.0f, e + 1.0f);
}

// One block handles G consecutive terms across the FULL batch.
// Phase 1: GEMM (64 -> 8 per term) with f32x2 packed FMA, x staged via smem chunks.
// Phase 2: tanh -> smem, per-(term,feature) batch stats (one warp each), BN affine.
// Phase 3: normalize, write t, fused aux head (8->2), tanh -> smem.
// Phase 4: aux batch stats, BN affine, write aux.
template<int G>
__global__ void __launch_bounds__(THREADS, 1)
term_layer_kernel(const float* __restrict__ xin, long long xstride, int colmult,
                  const float* __restrict__ Wp,  const float* __restrict__ bp,
                  const float* __restrict__ gp,  const float* __restrict__ bep,
                  const float* __restrict__ Wap, const float* __restrict__ bap,
                  const float* __restrict__ gap, const float* __restrict__ beap,
                  float* __restrict__ out_t, float* __restrict__ out_a, int M)
{
    extern __shared__ float sm[];
    float* sh_x   = sm;                          // [2048][17]; later reused as sh_t [G*8][2048]
    float* sh_a   = sm + B_ROWS * XPAD;          // [G*2][2048]
    float* sh_w   = sh_a + G * 2 * B_ROWS;       // [G][64][8]
    float* sh_b0  = sh_w + G * 512;              // [G*8]
    float* sh_g0  = sh_b0 + G * 8;
    float* sh_be0 = sh_g0 + G * 8;
    float* sh_wa  = sh_be0 + G * 8;              // [G][8][2]
    float* sh_ba  = sh_wa + G * 16;              // [G*2]
    float* sh_ga  = sh_ba + G * 2;
    float* sh_bea = sh_ga + G * 2;
    float* stA    = sh_bea + G * 2;              // 16
    float* stB    = stA + 16;                    // 16
    float* saA    = stB + 16;                    // 4
    float* saB    = saA + 4;                     // 4

    const int tid  = threadIdx.x;
    const int lane = tid & 31;
    const int warp = tid >> 5;
    const int m0   = blockIdx.x * G;
    const long long xbase = (long long)m0 * colmult;

    // ---- load per-term params into smem ----
    for (int i = tid; i < G * 512; i += THREADS) sh_w[i] = Wp[(long long)m0 * 512 + i];
    if (tid < G * 8) {
        sh_b0[tid]  = bp[m0 * 8 + tid];
        sh_g0[tid]  = gp[m0 * 8 + tid];
        sh_be0[tid] = bep[m0 * 8 + tid];
    }
    if (tid < G * 16) sh_wa[tid] = Wap[m0 * 16 + tid];
    if (tid < G * 2) {
        sh_ba[tid]  = bap[m0 * 2 + tid];
        sh_ga[tid]  = gap[m0 * 2 + tid];
        sh_bea[tid] = beap[m0 * 2 + tid];
    }

    // ---- Phase 1: GEMM, whole batch in registers ----
    ull acc[RPT][G * 4];
    #pragma unroll
    for (int r = 0; r < RPT; ++r)
        #pragma unroll
        for (int j = 0; j < G * 4; ++j) acc[r][j] = 0ull;

    #pragma unroll 1
    for (int c = 0; c < 64 / DC; ++c) {
        __syncthreads();   // also orders param writes before first use
        // cooperative load of x chunk [2048][DC]
        #pragma unroll
        for (int ii = 0; ii < (B_ROWS * (DC / 4)) / THREADS; ++ii) {
            int i = tid + ii * THREADS;
            int row = i >> 2;
            int q = i & 3;
            const float4 v = *reinterpret_cast<const float4*>(
                &xin[(long long)row * xstride + xbase + c * DC + q * 4]);
            float* dst = &sh_x[row * XPAD + q * 4];
            dst[0] = v.x; dst[1] = v.y; dst[2] = v.z; dst[3] = v.w;
        }
        __syncthreads();
        #pragma unroll
        for (int d = 0; d < DC; ++d) {
            ull w[G * 4];
            #pragma unroll
            for (int g = 0; g < G; ++g)
                #pragma unroll
                for (int p = 0; p < 4; ++p)
                    w[g * 4 + p] = *reinterpret_cast<const ull*>(
                        &sh_w[(g * 64 + c * DC + d) * 8 + 2 * p]);
            #pragma unroll
            for (int r = 0; r < RPT; ++r) {
                float xv = sh_x[(tid + THREADS * r) * XPAD + d];
                ull xx = pack2(xv, xv);
                #pragma unroll
                for (int j = 0; j < G * 4; ++j) acc[r][j] = fma2(xx, w[j], acc[r][j]);
            }
        }
    }
    __syncthreads();   // sh_x (as x) dead -> reuse as sh_t

    // ---- Phase 2: bias + tanh -> smem ----
    float* sh_t = sm;  // [G*8][2048]
    #pragma unroll
    for (int r = 0; r < RPT; ++r) {
        int b = tid + THREADS * r;
        #pragma unroll
        for (int g = 0; g < G; ++g)
            #pragma unroll
            for (int p = 0; p < 4; ++p) {
                float lo, hi; unpack2(acc[r][g * 4 + p], lo, hi);
                int P = g * 8 + 2 * p;
                sh_t[P * B_ROWS + b]       = ftanh(lo + sh_b0[P]);
                sh_t[(P + 1) * B_ROWS + b] = ftanh(hi + sh_b0[P + 1]);
            }
    }
    __syncthreads();

    // ---- batch stats per (g,h): one warp per pair ----
    for (int P = warp; P < G * 8; P += 8) {
        const float4* rowp = reinterpret_cast<const float4*>(sh_t + P * B_ROWS);
        float s = 0.f, ss = 0.f;
        for (int i = lane; i < B_ROWS / 4; i += 32) {
            float4 v = rowp[i];
            s  += (v.x + v.y) + (v.z + v.w);
            ss += v.x * v.x + v.y * v.y + v.z * v.z + v.w * v.w;
        }
        #pragma unroll
        for (int o = 16; o; o >>= 1) {
            s  += __shfl_xor_sync(0xffffffffu, s, o);
            ss += __shfl_xor_sync(0xffffffffu, ss, o);
        }
        if (lane == 0) {
            float mu  = s  * (1.f / B_ROWS);
            float var = ss * (1.f / B_ROWS) - mu * mu;
            float rs  = rsqrtf(var + BN_EPS);
            float a   = sh_g0[P] * rs;
            stA[P] = a;
            stB[P] = sh_be0[P] - mu * a;
        }
    }
    __syncthreads();

    // ---- Phase 3: normalize, write t, fused aux head ----
    float rA[G * 8], rB[G * 8], rwa[G * 16], rba[G * 2];
    #pragma unroll
    for (int P = 0; P < G * 8; ++P) { rA[P] = stA[P]; rB[P] = stB[P]; }
    #pragma unroll
    for (int i = 0; i < G * 16; ++i) rwa[i] = sh_wa[i];
    #pragma unroll
    for (int j = 0; j < G * 2; ++j) rba[j] = sh_ba[j];

    #pragma unroll
    for (int r = 0; r < RPT; ++r) {
        int b = tid + THREADS * r;
        float tn[G * 8];
        #pragma unroll
        for (int P = 0; P < G * 8; ++P) tn[P] = fmaf(rA[P], sh_t[P * B_ROWS + b], rB[P]);

        long long obase = ((long long)b * M + m0) * 8;
        #pragma unroll
        for (int q = 0; q < G * 2; ++q) {
            float4 v = make_float4(tn[q * 4], tn[q * 4 + 1], tn[q * 4 + 2], tn[q * 4 + 3]);
            *reinterpret_cast<float4*>(&out_t[obase + q * 4]) = v;
        }
        #pragma unroll
        for (int g = 0; g < G; ++g)
            #pragma unroll
            for (int k = 0; k < 2; ++k) {
                float a = rba[g * 2 + k];
                #pragma unroll
                for (int h = 0; h < 8; ++h)
                    a = fmaf(tn[g * 8 + h], rwa[(g * 8 + h) * 2 + k], a);
                sh_a[(g * 2 + k) * B_ROWS + b] = ftanh(a);
            }
    }
    __syncthreads();

    // ---- Phase 4: aux stats + write ----
    if (warp < G * 2) {
        int j = warp;
        const float4* rowp = reinterpret_cast<const float4*>(sh_a + j * B_ROWS);
        float s = 0.f, ss = 0.f;
        for (int i = lane; i < B_ROWS / 4; i += 32) {
            float4 v = rowp[i];
            s  += (v.x + v.y) + (v.z + v.w);
            ss += v.x * v.x + v.y * v.y + v.z * v.z + v.w * v.w;
        }
        #pragma unroll
        for (int o = 16; o; o >>= 1) {
            s  += __shfl_xor_sync(0xffffffffu, s, o);
            ss += __shfl_xor_sync(0xffffffffu, ss, o);
        }
        if (lane == 0) {
            float mu  = s  * (1.f / B_ROWS);
            float var = ss * (1.f / B_ROWS) - mu * mu;
            float rs  = rsqrtf(var + BN_EPS);
            float a   = sh_ga[j] * rs;
            saA[j] = a;
            saB[j] = sh_bea[j] - mu * a;
        }
    }
    __syncthreads();

    float rsa[G * 2], rsb[G * 2];
    #pragma unroll
    for (int j = 0; j < G * 2; ++j) { rsa[j] = saA[j]; rsb[j] = saB[j]; }
    #pragma unroll
    for (int r = 0; r < RPT; ++r) {
        int b = tid + THREADS * r;
        long long obase = ((long long)b * M + m0) * 2;
        if (G == 2) {
            float4 v;
            v.x = fmaf(rsa[0], sh_a[0 * B_ROWS + b], rsb[0]);
            v.y = fmaf(rsa[1], sh_a[1 * B_ROWS + b], rsb[1]);
            v.z = fmaf(rsa[2], sh_a[2 * B_ROWS + b], rsb[2]);
            v.w = fmaf(rsa[3], sh_a[3 * B_ROWS + b], rsb[3]);
            *reinterpret_cast<float4*>(&out_a[obase]) = v;
        } else {
            float2 v;
            v.x = fmaf(rsa[0], sh_a[0 * B_ROWS + b], rsb[0]);
            v.y = fmaf(rsa[1], sh_a[1 * B_ROWS + b], rsb[1]);
            *reinterpret_cast<float2*>(&out_a[obase]) = v;
        }
    }
}

// Output layout: (aux0, aux1, t0, t1) flattened, fp32
static const long long OFF_A0 = 0;
static const long long OFF_A1 = 2048LL * 8192 * 2;                 // 33,554,432
static const long long OFF_T0 = OFF_A1 + 2048LL * 1024 * 2;        // 37,748,736
static const long long OFF_T1 = OFF_T0 + 2048LL * 8192 * 8;        // 171,966,464

static inline int smem_bytes(int G) {
    return (B_ROWS * XPAD + G * 2 * B_ROWS + G * 512 + G * 24 + G * 16 + G * 6 + 40) * 4;
}

extern "C" void kernel_launch(void* const* d_in, const int* in_sizes, int n_in,
                              void* d_out, int out_size)
{
    const float* x    = (const float*)d_in[0];
    const float* W0   = (const float*)d_in[1];
    const float* b0   = (const float*)d_in[2];
    const float* g0   = (const float*)d_in[3];
    const float* be0  = (const float*)d_in[4];
    const float* Wa0  = (const float*)d_in[5];
    const float* ba0  = (const float*)d_in[6];
    const float* ga0  = (const float*)d_in[7];
    const float* bea0 = (const float*)d_in[8];
    const float* W1   = (const float*)d_in[9];
    const float* b1   = (const float*)d_in[10];
    const float* g1   = (const float*)d_in[11];
    const float* be1  = (const float*)d_in[12];
    const float* Wa1  = (const float*)d_in[13];
    const float* ba1  = (const float*)d_in[14];
    const float* ga1  = (const float*)d_in[15];
    const float* bea1 = (const float*)d_in[16];

    float* out  = (float*)d_out;
    float* aux0 = out + OFF_A0;
    float* aux1 = out + OFF_A1;
    float* t0   = out + OFF_T0;
    float* t1   = out + OFF_T1;

    int s2 = smem_bytes(2);
    int s1 = smem_bytes(1);
    cudaFuncSetAttribute(reinterpret_cast<const void*>(term_layer_kernel<2>),
                         cudaFuncAttributeMaxDynamicSharedMemorySize, s2);
    cudaFuncSetAttribute(reinterpret_cast<const void*>(term_layer_kernel<1>),
                         cudaFuncAttributeMaxDynamicSharedMemorySize, s1);

    // Layer 0: 8192 terms, 2 per block, all read the same x [2048,64]
    term_layer_kernel<2><<<8192 / 2, THREADS, s2>>>(
        x, 64, 0, W0, b0, g0, be0, Wa0, ba0, ga0, bea0, t0, aux0, 8192);

    // Layer 1: 1024 roots, 1 per block, each reads its 64-col slice of t0 [2048, 65536]
    term_layer_kernel<1><<<1024, THREADS, s1>>>(
        t0, 65536, 64, W1, b1, g1, be1, Wa1, ba1, ga1, bea1, t1, aux1, 1024);
}

// round 2
// speedup vs baseline: 1.0194x; 1.0194x over previous
#include <cuda_runtime.h>

#define THREADS 512
#define NW (THREADS / 32)
#define B_ROWS 2048
#define RPT (B_ROWS / THREADS)   // 4 rows per thread
#define BN_EPS 1e-5f

typedef unsigned long long ull;

__device__ __forceinline__ ull pack2(float lo, float hi) {
    ull r; asm("mov.b64 %0, {%1, %2};" : "=l"(r) : "f"(lo), "f"(hi)); return r;
}
__device__ __forceinline__ void unpack2(ull v, float& lo, float& hi) {
    asm("mov.b64 {%0, %1}, %2;" : "=f"(lo), "=f"(hi) : "l"(v));
}
__device__ __forceinline__ ull fma2(ull a, ull b, ull c) {
    ull d; asm("fma.rn.f32x2 %0, %1, %2, %3;" : "=l"(d) : "l"(a), "l"(b), "l"(c)); return d;
}
// accurate tanh (~1e-7 rel): tanh.approx at ~5e-4 is too close to the 1e-3 gate
__device__ __forceinline__ float ftanh(float x) {
    float e = __expf(2.0f * x);
    return 1.0f - __fdividef(2.0f, e + 1.0f);
}

// One block = G consecutive terms, full batch of 2048 rows held in registers
// (4 rows/thread x 8G features). x is read straight from L2 (each row owned by
// exactly one thread -> block reads x exactly once; smem staging adds nothing).
// BN stats via shfl butterfly + tiny cross-warp smem reduction.
template<int G>
__global__ void __launch_bounds__(THREADS, 1)
term_layer_kernel(const float* __restrict__ xin, long long xstride, int colmult,
                  const float* __restrict__ Wp,  const float* __restrict__ bp,
                  const float* __restrict__ gp,  const float* __restrict__ bep,
                  const float* __restrict__ Wap, const float* __restrict__ bap,
                  const float* __restrict__ gap, const float* __restrict__ beap,
                  float* __restrict__ out_t, float* __restrict__ out_a, int M)
{
    constexpr int F = 8 * G;     // term-NN features per block
    constexpr int FA = 2 * G;    // aux features per block

    __shared__ float sh_w[G * 512];           // [G][64][8]
    __shared__ float sh_b0[F], sh_g0[F], sh_be0[F];
    __shared__ float sh_wa[G * 16];           // [G][8][2]
    __shared__ float sh_ba[FA], sh_ga[FA], sh_bea[FA];
    __shared__ float red[F * NW * 2];         // cross-warp partials (reused for aux)
    __shared__ float stA[F], stB[F];
    __shared__ float saA[FA], saB[FA];

    const int tid  = threadIdx.x;
    const int lane = tid & 31;
    const int warp = tid >> 5;
    const int m0   = blockIdx.x * G;

    // ---- params to smem ----
    for (int i = tid; i < G * 512; i += THREADS) sh_w[i] = Wp[(long long)m0 * 512 + i];
    if (tid < F) {
        sh_b0[tid]  = bp[m0 * 8 + tid];
        sh_g0[tid]  = gp[m0 * 8 + tid];
        sh_be0[tid] = bep[m0 * 8 + tid];
    }
    if (tid < G * 16) sh_wa[tid] = Wap[m0 * 16 + tid];
    if (tid < FA) {
        sh_ba[tid]  = bap[m0 * 2 + tid];
        sh_ga[tid]  = gap[m0 * 2 + tid];
        sh_bea[tid] = beap[m0 * 2 + tid];
    }
    __syncthreads();

    // ---- Phase 1: GEMM (64 -> F), packed f32x2 FMA, x streamed from L2 ----
    const float* xptr[RPT];
    #pragma unroll
    for (int r = 0; r < RPT; ++r)
        xptr[r] = xin + (long long)(tid + r * THREADS) * xstride + (long long)m0 * colmult;

    ull acc[RPT][4 * G];
    #pragma unroll
    for (int r = 0; r < RPT; ++r)
        #pragma unroll
        for (int j = 0; j < 4 * G; ++j) acc[r][j] = 0ull;

    #pragma unroll 1
    for (int c = 0; c < 16; ++c) {           // 16 chunks of 4 input dims
        float xv[RPT][4];
        #pragma unroll
        for (int r = 0; r < RPT; ++r) {
            const float4 v = *reinterpret_cast<const float4*>(xptr[r] + c * 4);
            xv[r][0] = v.x; xv[r][1] = v.y; xv[r][2] = v.z; xv[r][3] = v.w;
        }
        #pragma unroll
        for (int dd = 0; dd < 4; ++dd) {
            ull w[4 * G];
            #pragma unroll
            for (int g = 0; g < G; ++g)
                #pragma unroll
                for (int p = 0; p < 4; ++p)
                    w[g * 4 + p] = *reinterpret_cast<const ull*>(
                        &sh_w[(g * 64 + c * 4 + dd) * 8 + 2 * p]);
            #pragma unroll
            for (int r = 0; r < RPT; ++r) {
                ull xx = pack2(xv[r][dd], xv[r][dd]);
                #pragma unroll
                for (int j = 0; j < 4 * G; ++j) acc[r][j] = fma2(xx, w[j], acc[r][j]);
            }
        }
    }

    // ---- Phase 2: bias + tanh (in registers) ----
    float tv[RPT][F];
    #pragma unroll
    for (int r = 0; r < RPT; ++r)
        #pragma unroll
        for (int g = 0; g < G; ++g)
            #pragma unroll
            for (int p = 0; p < 4; ++p) {
                float lo, hi; unpack2(acc[r][g * 4 + p], lo, hi);
                int P = g * 8 + 2 * p;
                tv[r][P]     = ftanh(lo + sh_b0[P]);
                tv[r][P + 1] = ftanh(hi + sh_b0[P + 1]);
            }

    // ---- batch stats: shfl butterfly, then cross-warp reduce in smem ----
    #pragma unroll
    for (int f = 0; f < F; ++f) {
        float s = 0.f, ss = 0.f;
        #pragma unroll
        for (int r = 0; r < RPT; ++r) { float v = tv[r][f]; s += v; ss += v * v; }
        #pragma unroll
        for (int o = 16; o; o >>= 1) {
            s  += __shfl_xor_sync(0xffffffffu, s, o);
            ss += __shfl_xor_sync(0xffffffffu, ss, o);
        }
        if (lane == 0) { red[f * NW + warp] = s; red[(F + f) * NW + warp] = ss; }
    }
    __syncthreads();
    if (tid < F) {
        int f = tid;
        float s = 0.f, ss = 0.f;
        #pragma unroll
        for (int w = 0; w < NW; ++w) { s += red[f * NW + w]; ss += red[(F + f) * NW + w]; }
        float mu  = s  * (1.f / B_ROWS);
        float var = ss * (1.f / B_ROWS) - mu * mu;
        float a   = sh_g0[f] * rsqrtf(var + BN_EPS);
        stA[f] = a;
        stB[f] = sh_be0[f] - mu * a;
    }
    __syncthreads();

    // ---- Phase 3: normalize, write t, fused aux head (tanh -> regs) ----
    float av[RPT][FA];
    #pragma unroll
    for (int r = 0; r < RPT; ++r) {
        int b = tid + r * THREADS;
        float tn[F];
        #pragma unroll
        for (int f = 0; f < F; ++f) tn[f] = fmaf(stA[f], tv[r][f], stB[f]);

        long long obase = ((long long)b * M + m0) * 8;
        #pragma unroll
        for (int q = 0; q < 2 * G; ++q) {
            float4 v = make_float4(tn[q * 4], tn[q * 4 + 1], tn[q * 4 + 2], tn[q * 4 + 3]);
            *reinterpret_cast<float4*>(&out_t[obase + q * 4]) = v;
        }
        #pragma unroll
        for (int g = 0; g < G; ++g)
            #pragma unroll
            for (int k = 0; k < 2; ++k) {
                float a = sh_ba[g * 2 + k];
                #pragma unroll
                for (int h = 0; h < 8; ++h)
                    a = fmaf(tn[g * 8 + h], sh_wa[(g * 8 + h) * 2 + k], a);
                av[r][g * 2 + k] = ftanh(a);
            }
    }

    // ---- Phase 4: aux stats + write ----
    #pragma unroll
    for (int f = 0; f < FA; ++f) {
        float s = 0.f, ss = 0.f;
        #pragma unroll
        for (int r = 0; r < RPT; ++r) { float v = av[r][f]; s += v; ss += v * v; }
        #pragma unroll
        for (int o = 16; o; o >>= 1) {
            s  += __shfl_xor_sync(0xffffffffu, s, o);
            ss += __shfl_xor_sync(0xffffffffu, ss, o);
        }
        if (lane == 0) { red[f * NW + warp] = s; red[(FA + f) * NW + warp] = ss; }
    }
    __syncthreads();
    if (tid < FA) {
        int f = tid;
        float s = 0.f, ss = 0.f;
        #pragma unroll
        for (int w = 0; w < NW; ++w) { s += red[f * NW + w]; ss += red[(FA + f) * NW + w]; }
        float mu  = s  * (1.f / B_ROWS);
        float var = ss * (1.f / B_ROWS) - mu * mu;
        float a   = sh_ga[f] * rsqrtf(var + BN_EPS);
        saA[f] = a;
        saB[f] = sh_bea[f] - mu * a;
    }
    __syncthreads();

    #pragma unroll
    for (int r = 0; r < RPT; ++r) {
        int b = tid + r * THREADS;
        long long obase = ((long long)b * M + m0) * 2;
        if (G == 2) {
            float4 v;
            v.x = fmaf(saA[0], av[r][0], saB[0]);
            v.y = fmaf(saA[1], av[r][1], saB[1]);
            v.z = fmaf(saA[2], av[r][2], saB[2]);
            v.w = fmaf(saA[3], av[r][3], saB[3]);
            *reinterpret_cast<float4*>(&out_a[obase]) = v;
        } else {
            float2 v;
            v.x = fmaf(saA[0], av[r][0], saB[0]);
            v.y = fmaf(saA[1], av[r][1], saB[1]);
            *reinterpret_cast<float2*>(&out_a[obase]) = v;
        }
    }
}

// Output layout: (aux0, aux1, t0, t1) flattened, fp32
static const long long OFF_A0 = 0;
static const long long OFF_A1 = 2048LL * 8192 * 2;            // 33,554,432
static const long long OFF_T0 = OFF_A1 + 2048LL * 1024 * 2;   // 37,748,736
static const long long OFF_T1 = OFF_T0 + 2048LL * 8192 * 8;   // 171,966,464

extern "C" void kernel_launch(void* const* d_in, const int* in_sizes, int n_in,
                              void* d_out, int out_size)
{
    const float* x    = (const float*)d_in[0];
    const float* W0   = (const float*)d_in[1];
    const float* b0   = (const float*)d_in[2];
    const float* g0   = (const float*)d_in[3];
    const float* be0  = (const float*)d_in[4];
    const float* Wa0  = (const float*)d_in[5];
    const float* ba0  = (const float*)d_in[6];
    const float* ga0  = (const float*)d_in[7];
    const float* bea0 = (const float*)d_in[8];
    const float* W1   = (const float*)d_in[9];
    const float* b1   = (const float*)d_in[10];
    const float* g1   = (const float*)d_in[11];
    const float* be1  = (const float*)d_in[12];
    const float* Wa1  = (const float*)d_in[13];
    const float* ba1  = (const float*)d_in[14];
    const float* ga1  = (const float*)d_in[15];
    const float* bea1 = (const float*)d_in[16];

    float* out  = (float*)d_out;
    float* aux0 = out + OFF_A0;
    float* aux1 = out + OFF_A1;
    float* t0   = out + OFF_T0;
    float* t1   = out + OFF_T1;

    // Layer 0: 8192 terms, 2 per block, all blocks stream the same x [2048,64] from L2
    term_layer_kernel<2><<<8192 / 2, THREADS>>>(
        x, 64, 0, W0, b0, g0, be0, Wa0, ba0, ga0, bea0, t0, aux0, 8192);

    // Layer 1: 1024 roots, 1 per block, each reads its 64-col slice of t0 [2048, 65536]
    term_layer_kernel<1><<<1024, THREADS>>>(
        t0, 65536, 64, W1, b1, g1, be1, Wa1, ba1, ga1, bea1, t1, aux1, 1024);
}